// round 1
// baseline (speedup 1.0000x reference)
#include <cuda_runtime.h>

#define THREADS 512
#define G 8
#define NS 4096
#define NF 64
#define NBATCH 32

// pywt db4 dec filters, time-reversed (cross-correlation form)
__device__ __constant__ float cH0[8] = {
     0.23037781330885523f,  0.7148465705525415f,   0.6308807679295904f,
    -0.02798376941698385f, -0.18703481171888114f,  0.030841381835986965f,
     0.032883011666982945f, -0.010597401784997278f };
__device__ __constant__ float cH1[8] = {
    -0.010597401784997278f, -0.032883011666982945f, 0.030841381835986965f,
     0.18703481171888114f,  -0.02798376941698385f,  -0.6308807679295904f,
     0.7148465705525415f,   -0.23037781330885523f };

// One analysis level reading from smem `in` (length TIN rows x G feats),
// writing lo to smem loOut (TIN/2 rows), masked hi to gmem detail plane,
// and accumulating masked hi into the smem high-freq accumulator.
template <int TIN>
__device__ __forceinline__ void do_level(const float* __restrict__ in,
                                         float* __restrict__ loOut,
                                         float* __restrict__ hf,
                                         float* __restrict__ det,
                                         unsigned mask)
{
    const int OUTN = TIN / 2;
    for (int n = threadIdx.x; n < OUTN; n += THREADS) {
        float alo[G], ahi[G];
#pragma unroll
        for (int j = 0; j < G; ++j) { alo[j] = 0.f; ahi[j] = 0.f; }
#pragma unroll
        for (int t = 0; t < 8; ++t) {
            int idx = 2 * n + t - 3;
            if (idx >= 0 && idx < TIN) {
                const float* p = in + idx * G;
#pragma unroll
                for (int j = 0; j < G; ++j) {
                    float v = p[j];
                    alo[j] = fmaf(cH0[t], v, alo[j]);
                    ahi[j] = fmaf(cH1[t], v, ahi[j]);
                }
            }
        }
        float dv[G];
#pragma unroll
        for (int j = 0; j < G; ++j) {
            loOut[n * G + j] = alo[j];
            dv[j] = ((mask >> j) & 1u) ? ahi[j] : 0.f;
            hf[n * G + j] += dv[j];
        }
        float4* pd = (float4*)(det + (size_t)n * NF);
        pd[0] = make_float4(dv[0], dv[1], dv[2], dv[3]);
        pd[1] = make_float4(dv[4], dv[5], dv[6], dv[7]);
    }
    // zero tail of the detail plane
    const float4 z = make_float4(0.f, 0.f, 0.f, 0.f);
    for (int n = OUTN + (int)threadIdx.x; n < NS; n += THREADS) {
        float4* pd = (float4*)(det + (size_t)n * NF);
        pd[0] = z; pd[1] = z;
    }
}

__global__ void __launch_bounds__(THREADS, 1)
dwt_kernel(const float* __restrict__ x, const float* __restrict__ scores,
           float* __restrict__ out)
{
    extern __shared__ float sm[];
    float* lo1 = sm;                   // 2048*G
    float* lo2 = lo1 + 2048 * G;       // 1024*G
    float* lo3 = lo2 + 1024 * G;       // 512*G
    float* lo4 = lo3 + 512 * G;        // 256*G
    float* lo5 = lo4 + 256 * G;        // 128*G
    float* hf  = lo5 + 128 * G;        // 2048*G

    const int b = blockIdx.x >> 3;
    const int fbase = (blockIdx.x & 7) * G;
    const int tid = threadIdx.x;

    // per-feature decomposition level: 2 + round_half_even(score*3), clamp [2,5]
    int lf[G];
#pragma unroll
    for (int j = 0; j < G; ++j) {
        float sc = __ldg(scores + fbase + j);
        int l = 2 + (int)rintf(sc * 3.0f);
        lf[j] = l < 2 ? 2 : (l > 5 ? 5 : l);
    }
    unsigned msk[5];
#pragma unroll
    for (int i = 0; i < 5; ++i) {
        unsigned m = 0;
#pragma unroll
        for (int j = 0; j < G; ++j) if (i < lf[j]) m |= 1u << j;
        msk[i] = m;     // msk[0], msk[1] are always 0xFF (lf >= 2)
    }

    const size_t PLANE = (size_t)NBATCH * NS * NF;         // 8388608
    const size_t rowBase = (size_t)b * NS * NF + fbase;

    // ---------------- level 1: conv straight from gmem ----------------
    {
        float* det = out + PLANE + rowBase;                // details[0]
        for (int n = tid; n < 2048; n += THREADS) {
            float alo[G], ahi[G];
#pragma unroll
            for (int j = 0; j < G; ++j) { alo[j] = 0.f; ahi[j] = 0.f; }
#pragma unroll
            for (int t = 0; t < 8; ++t) {
                int idx = 2 * n + t - 3;
                if (idx >= 0 && idx < NS) {
                    const float4* p = (const float4*)(x + rowBase + (size_t)idx * NF);
                    float4 v0 = __ldg(p);
                    float4 v1 = __ldg(p + 1);
                    float vv[G] = { v0.x, v0.y, v0.z, v0.w, v1.x, v1.y, v1.z, v1.w };
#pragma unroll
                    for (int j = 0; j < G; ++j) {
                        alo[j] = fmaf(cH0[t], vv[j], alo[j]);
                        ahi[j] = fmaf(cH1[t], vv[j], ahi[j]);
                    }
                }
            }
#pragma unroll
            for (int j = 0; j < G; ++j) {
                lo1[n * G + j] = alo[j];
                hf[n * G + j]  = ahi[j];   // level 0 always active
            }
            float4* pd = (float4*)(det + (size_t)n * NF);
            pd[0] = make_float4(ahi[0], ahi[1], ahi[2], ahi[3]);
            pd[1] = make_float4(ahi[4], ahi[5], ahi[6], ahi[7]);
        }
        const float4 z = make_float4(0.f, 0.f, 0.f, 0.f);
        for (int n = 2048 + tid; n < NS; n += THREADS) {
            float4* pd = (float4*)(det + (size_t)n * NF);
            pd[0] = z; pd[1] = z;
        }
    }
    __syncthreads();

    do_level<2048>(lo1, lo2, hf, out + 2 * PLANE + rowBase, msk[1]);
    __syncthreads();
    do_level<1024>(lo2, lo3, hf, out + 3 * PLANE + rowBase, msk[2]);
    __syncthreads();
    do_level< 512>(lo3, lo4, hf, out + 4 * PLANE + rowBase, msk[3]);
    __syncthreads();
    do_level< 256>(lo4, lo5, hf, out + 5 * PLANE + rowBase, msk[4]);
    __syncthreads();

    // ---------------- final pass: approx / low_freq / high_freq ----------------
    const float* lop[4] = { lo2, lo3, lo4, lo5 };
    const int    lon[4] = { 1024, 512, 256, 128 };
    const float* lpj[G];
    int limj[G];
#pragma unroll
    for (int j = 0; j < G; ++j) {
        lpj[j]  = lop[lf[j] - 2];
        limj[j] = lon[lf[j] - 2];
    }

    float* outA = out + rowBase;                 // approx
    float* outH = out + 6 * PLANE + rowBase;     // high_freq
    float* outL = out + 7 * PLANE + rowBase;     // low_freq
    const float4 z = make_float4(0.f, 0.f, 0.f, 0.f);

    for (int s = tid; s < NS; s += THREADS) {
        float av[G];
#pragma unroll
        for (int j = 0; j < G; ++j)
            av[j] = (s < limj[j]) ? lpj[j][s * G + j] : 0.f;
        float4 a0 = make_float4(av[0], av[1], av[2], av[3]);
        float4 a1 = make_float4(av[4], av[5], av[6], av[7]);
        float4* pa = (float4*)(outA + (size_t)s * NF);
        pa[0] = a0; pa[1] = a1;
        float4* pl = (float4*)(outL + (size_t)s * NF);
        pl[0] = a0; pl[1] = a1;

        float4 h0 = z, h1 = z;
        if (s < 2048) {
            const float* hp = hf + s * G;
            h0 = make_float4(hp[0], hp[1], hp[2], hp[3]);
            h1 = make_float4(hp[4], hp[5], hp[6], hp[7]);
        }
        float4* ph = (float4*)(outH + (size_t)s * NF);
        ph[0] = h0; ph[1] = h1;
    }
}

extern "C" void kernel_launch(void* const* d_in, const int* in_sizes, int n_in,
                              void* d_out, int out_size)
{
    const float* x      = (const float*)d_in[0];
    const float* scores = (const float*)d_in[1];
    float* out          = (float*)d_out;

    const size_t smem = (size_t)(2048 + 1024 + 512 + 256 + 128 + 2048) * G * sizeof(float); // 192512
    cudaFuncSetAttribute(dwt_kernel, cudaFuncAttributeMaxDynamicSharedMemorySize, (int)smem);

    dwt_kernel<<<NBATCH * (NF / G), THREADS, smem>>>(x, scores, out);
}